// round 7
// baseline (speedup 1.0000x reference)
#include <cuda_runtime.h>
#include <cuda_fp16.h>
#include <math_constants.h>

#define NN 100000
#define EMAX 1700000
#define SCAN_BS 1024
#define NB ((NN + SCAN_BS - 1) / SCAN_BS)   // 98

// ---------------- device scratch (static globals; no allocation) -------------
__device__ __align__(16) __half g_y [NN * 64];  // (XW)*ns in fp16, gather source
__device__ __align__(16) float g_h1[NN * 64];   // layer-1 output (fp32)
__device__ __align__(16) float g_h2[NN * 64];   // layer-2 output (fp32)
__device__ float g_ns[NN];
__device__ float g_nd[NN];
__device__ int g_cnt_out[NN];
__device__ int g_cnt_in [NN];
__device__ int g_cursor [NN];
__device__ int g_rowptr [NN + 1];
__device__ int g_blocksum[NB];
__device__ int g_esrc[EMAX];                    // src indices sorted by dst
__device__ int g_is64;

__device__ __forceinline__ int load_idx(const void* p, int i, int is64) {
    return is64 ? (int)((const long long*)p)[i] : ((const int*)p)[i];
}

// ---------------- zero histograms + index-width detection ---------------------
__global__ void zero_detect_kernel(const void* src, int E) {
    int i = blockIdx.x * blockDim.x + threadIdx.x;
    if (i < NN) { g_cnt_out[i] = 0; g_cnt_in[i] = 0; }
    if (blockIdx.x == 0 && threadIdx.x == 0) {
        const long long* p = (const long long*)src;
        int n = E < 8 ? E : 8;
        int ok = 1;
        for (int j = 0; j < n; j++) {
            long long v = p[j];
            if (v < 0 || v >= (long long)NN) { ok = 0; break; }
        }
        g_is64 = ok;
    }
}

// ---------------- shared GEMM body -> fp16 output ------------------------------
// 32 rows/block, 256 thr: lane covers 2 cols, 8 row-groups x 4 rows.
template<int IN, int OUT, bool SCALE>
__device__ __forceinline__ void gemm_body(
        const float* __restrict__ X, const float* __restrict__ W,
        __half2* __restrict__ Yh, int row0, float* Ws, float* Xs) {
    int tid = threadIdx.x;
    for (int i = tid * 4; i < IN * OUT; i += 256 * 4)
        *(float4*)&Ws[i] = *(const float4*)&W[i];

    constexpr int IN4 = IN / 4;
    for (int i = tid; i < 32 * IN4; i += 256) {
        int r = i / IN4, c = i % IN4;
        int gr = row0 + r;
        float4 v = (gr < NN) ? __ldg((const float4*)&X[(size_t)gr * IN + c * 4])
                             : make_float4(0.f, 0.f, 0.f, 0.f);
        *(float4*)&Xs[r * IN + c * 4] = v;
    }
    __syncthreads();

    int lane = tid & 31, rg = tid >> 5;
    int c0 = 2 * lane;
    if (c0 >= OUT) return;

    float acc[4][2] = {};
    #pragma unroll
    for (int k4 = 0; k4 < IN4; k4++) {
        float xv[4][4];
        #pragma unroll
        for (int r = 0; r < 4; r++) {
            float4 t = *(float4*)&Xs[(rg * 4 + r) * IN + k4 * 4];
            xv[r][0] = t.x; xv[r][1] = t.y; xv[r][2] = t.z; xv[r][3] = t.w;
        }
        #pragma unroll
        for (int kk = 0; kk < 4; kk++) {
            float2 w = *(float2*)&Ws[(k4 * 4 + kk) * OUT + c0];
            #pragma unroll
            for (int r = 0; r < 4; r++) {
                acc[r][0] += xv[r][kk] * w.x;
                acc[r][1] += xv[r][kk] * w.y;
            }
        }
    }
    constexpr int STR = OUT / 2;       // half2 per row
    #pragma unroll
    for (int r = 0; r < 4; r++) {
        int gr = row0 + rg * 4 + r;
        if (gr < NN) {
            float s = SCALE ? g_ns[gr] : 1.f;
            Yh[(size_t)gr * STR + lane] =
                __floats2half2_rn(acc[r][0] * s, acc[r][1] * s);
        }
    }
}

// ---------------- fused launch: edge histogram || layer-0 GEMM (unscaled) ----
__global__ void __launch_bounds__(256) histgemm_kernel(
        const void* __restrict__ src, const void* __restrict__ dst, int E,
        int EB, const float* __restrict__ X, const float* __restrict__ W,
        __half2* __restrict__ Yh) {
    __shared__ float Ws[128 * 64];
    __shared__ float Xs[32 * 128];
    if ((int)blockIdx.x < EB) {
        int e = blockIdx.x * 256 + threadIdx.x;
        if (e >= E) return;
        int is64 = g_is64;
        atomicAdd(&g_cnt_out[load_idx(src, e, is64)], 1);
        atomicAdd(&g_cnt_in [load_idx(dst, e, is64)], 1);
        return;
    }
    gemm_body<128, 64, false>(X, W, Yh, (blockIdx.x - EB) * 32, Ws, Xs);
}

// ---------------- standalone scaled GEMM (layers 1, 2) ------------------------
template<int IN, int OUT>
__global__ void __launch_bounds__(256) gemm_scale_kernel(
        const float* __restrict__ X, const float* __restrict__ W,
        __half2* __restrict__ Yh) {
    __shared__ float Ws[IN * OUT];
    __shared__ float Xs[32 * IN];
    gemm_body<IN, OUT, true>(X, W, Yh, blockIdx.x * 32, Ws, Xs);
}

// ---------------- exclusive scan of cnt_in -> rowptr --------------------------
__global__ void __launch_bounds__(SCAN_BS) scan1_kernel() {
    __shared__ int sh[SCAN_BS];
    int tid = threadIdx.x;
    int i = blockIdx.x * SCAN_BS + tid;
    int v = (i < NN) ? g_cnt_in[i] : 0;
    sh[tid] = v;
    __syncthreads();
    #pragma unroll
    for (int off = 1; off < SCAN_BS; off <<= 1) {
        int t = (tid >= off) ? sh[tid - off] : 0;
        __syncthreads();
        sh[tid] += t;
        __syncthreads();
    }
    if (i < NN) g_rowptr[i] = sh[tid] - v;          // exclusive (per-block)
    if (tid == SCAN_BS - 1) g_blocksum[blockIdx.x] = sh[tid];
}

// warp-parallel scan of the 98 block sums
__global__ void scan2_kernel() {
    int lane = threadIdx.x;
    int carry = 0;
    const int CH = (NB + 31) / 32;
    for (int c = 0; c < CH; c++) {
        int i = c * 32 + lane;
        int v0 = (i < NB) ? g_blocksum[i] : 0;
        int v = v0;
        #pragma unroll
        for (int off = 1; off < 32; off <<= 1) {
            int t = __shfl_up_sync(0xffffffffu, v, off);
            if (lane >= off) v += t;
        }
        if (i < NB) g_blocksum[i] = carry + v - v0;  // exclusive
        carry += __shfl_sync(0xffffffffu, v, 31);
    }
    if (lane == 0) g_rowptr[NN] = carry;             // == E
}

// scan3: finalize rowptr, norms, cursors, AND scale Y0 (fp16) by ns
__global__ void __launch_bounds__(SCAN_BS) scan3_kernel(__half2* __restrict__ Yh) {
    int i = blockIdx.x * SCAN_BS + threadIdx.x;
    if (i >= NN) return;
    g_rowptr[i] += g_blocksum[blockIdx.x];
    g_cursor[i] = 0;
    int o = g_cnt_out[i], d = g_cnt_in[i];
    float nsv = (o > 0) ? rsqrtf((float)o) : 0.f;
    g_ns[i] = nsv;
    g_nd[i] = (d > 0) ? rsqrtf((float)d) : 0.f;
    __half2 h2s = __floats2half2_rn(nsv, nsv);
    __half2* yr = &Yh[(size_t)i * 32];
    #pragma unroll
    for (int j = 0; j < 32; j++)
        yr[j] = __hmul2(yr[j], h2s);
}

// ---------------- edge placement: CSR by dst ----------------------------------
__global__ void place_kernel(const void* __restrict__ src,
                             const void* __restrict__ dst, int E) {
    int e = blockIdx.x * blockDim.x + threadIdx.x;
    if (e >= E) return;
    int is64 = g_is64;
    int s = load_idx(src, e, is64);
    int d = load_idx(dst, e, is64);
    int pos = g_rowptr[d] + atomicAdd(&g_cursor[d], 1);
    g_esrc[pos] = s;
}

// ---------------- fused SpMM-gather (fp16 payload) + epilogue -----------------
// One warp per dst row; lane covers 2 cols via one half2 (4B) -> warp reads one
// 128B sector per edge (OUT=64). Accumulate fp32.
template<int OUT, bool RELU>
__global__ void __launch_bounds__(256) spmm_epi_kernel(
        const __half2* __restrict__ Yh, const float* __restrict__ bias,
        float* __restrict__ Out) {
    int row = blockIdx.x * 8 + (threadIdx.x >> 5);
    if (row >= NN) return;
    int lane = threadIdx.x & 31;
    constexpr int STR = OUT / 2;        // half2 per row
    int c0 = 2 * lane;
    bool valid = lane < STR;

    int beg = g_rowptr[row], end = g_rowptr[row + 1];
    float a0 = 0.f, a1 = 0.f, b0_ = 0.f, b1_ = 0.f;

    for (int base = beg; base < end; base += 32) {
        int rem = end - base; if (rem > 32) rem = 32;
        int my = (lane < rem) ? g_esrc[base + lane] : 0;
        int j = 0;
        for (; j + 4 <= rem; j += 4) {
            int s0 = __shfl_sync(0xffffffffu, my, j);
            int s1 = __shfl_sync(0xffffffffu, my, j + 1);
            int s2 = __shfl_sync(0xffffffffu, my, j + 2);
            int s3 = __shfl_sync(0xffffffffu, my, j + 3);
            if (valid) {
                float2 v0 = __half22float2(__ldg(&Yh[(size_t)s0 * STR + lane]));
                float2 v1 = __half22float2(__ldg(&Yh[(size_t)s1 * STR + lane]));
                float2 v2 = __half22float2(__ldg(&Yh[(size_t)s2 * STR + lane]));
                float2 v3 = __half22float2(__ldg(&Yh[(size_t)s3 * STR + lane]));
                a0 += v0.x; a1 += v0.y;
                b0_ += v1.x; b1_ += v1.y;
                a0 += v2.x; a1 += v2.y;
                b0_ += v3.x; b1_ += v3.y;
            }
        }
        for (; j < rem; j++) {
            int s = __shfl_sync(0xffffffffu, my, j);
            if (valid) {
                float2 v = __half22float2(__ldg(&Yh[(size_t)s * STR + lane]));
                a0 += v.x; a1 += v.y;
            }
        }
    }
    a0 += b0_; a1 += b1_;

    float ndv = g_nd[row];
    float v0 = -CUDART_INF_F, v1 = -CUDART_INF_F;
    if (valid) {
        v0 = a0 * ndv + bias[c0];
        v1 = a1 * ndv + bias[c0 + 1];
        if (RELU) { v0 = fmaxf(v0, 0.f); v1 = fmaxf(v1, 0.f); }
    }
    float m = fmaxf(v0, v1);
    #pragma unroll
    for (int o = 16; o; o >>= 1) m = fmaxf(m, __shfl_xor_sync(0xffffffffu, m, o));
    float s = valid ? (__expf(v0 - m) + __expf(v1 - m)) : 0.f;
    #pragma unroll
    for (int o = 16; o; o >>= 1) s += __shfl_xor_sync(0xffffffffu, s, o);
    float ls = logf(s);
    if (valid)
        *(float2*)&Out[(size_t)row * OUT + c0] = make_float2(v0 - m - ls, v1 - m - ls);
}

// ---------------- launcher ----------------------------------------------------
extern "C" void kernel_launch(void* const* d_in, const int* in_sizes, int n_in,
                              void* d_out, int out_size) {
    const float* feats = (const float*)d_in[0];
    const void*  src   = d_in[1];
    const void*  dst   = d_in[2];
    const float* W0    = (const float*)d_in[3];
    const float* b0    = (const float*)d_in[4];
    const float* W1    = (const float*)d_in[5];
    const float* b1    = (const float*)d_in[6];
    const float* W2    = (const float*)d_in[7];
    const float* b2    = (const float*)d_in[8];
    float* out = (float*)d_out;
    int E = in_sizes[1];

    __half2* p_y = nullptr;
    float *p_h1 = nullptr, *p_h2 = nullptr;
    cudaGetSymbolAddress((void**)&p_y,  g_y);
    cudaGetSymbolAddress((void**)&p_h1, g_h1);
    cudaGetSymbolAddress((void**)&p_h2, g_h2);

    const int GB = (NN + 31) / 32;    // gemm blocks (32 rows each)
    const int SB = (NN + 7) / 8;      // spmm blocks (warp per row)
    const int EB = (E + 255) / 256;   // per-edge blocks
    const int ZB = (NN + 255) / 256;  // zero blocks

    // ---- CSR build with layer-0 GEMM (unscaled, fp16 out) overlapped
    zero_detect_kernel<<<ZB, 256>>>(src, E);
    histgemm_kernel<<<EB + GB, 256>>>(src, dst, E, EB, feats, W0, p_y);
    scan1_kernel<<<NB, SCAN_BS>>>();
    scan2_kernel<<<1, 32>>>();
    scan3_kernel<<<NB, SCAN_BS>>>(p_y);   // + Y0 *= ns (fp16)
    place_kernel<<<EB, 256>>>(src, dst, E);

    // ---- layer 0: relu + log_softmax -> g_h1
    spmm_epi_kernel<64, true><<<SB, 256>>>(p_y, b0, p_h1);

    // ---- layer 1: 64 -> 64, relu + log_softmax -> g_h2
    gemm_scale_kernel<64, 64><<<GB, 256>>>(p_h1, W1, p_y);
    spmm_epi_kernel<64, true><<<SB, 256>>>(p_y, b1, p_h2);

    // ---- layer 2: 64 -> 40, log_softmax -> d_out
    gemm_scale_kernel<64, 40><<<GB, 256>>>(p_h2, W2, p_y);
    spmm_epi_kernel<40, false><<<SB, 256>>>(p_y, b2, out);
}

// round 10
// speedup vs baseline: 1.2255x; 1.2255x over previous
#include <cuda_runtime.h>
#include <cuda_fp16.h>
#include <math_constants.h>
#include <cstdint>

#define NN 100000
#define EMAX 1700000
#define SCAN_BS 1024
#define NB ((NN + SCAN_BS - 1) / SCAN_BS)   // 98

// ---------------- device scratch (static globals; no allocation) -------------
__device__ __align__(16) __half g_y [NN * 64];  // (XW)*ns fp16, gather source
__device__ __align__(16) __half g_h1[NN * 64];  // layer-1 output (fp16)
__device__ __align__(16) __half g_h2[NN * 64];  // layer-2 output (fp16)
__device__ __align__(16) __half g_wt0[64 * 128]; // W0^T [out=64][in=128] fp16
__device__ __align__(16) __half g_wt1[64 * 64];  // W1^T [64][64]
__device__ __align__(16) __half g_wt2[40 * 64];  // W2^T [40][64]
__device__ float g_ns[NN];
__device__ float g_nd[NN];
__device__ int g_cnt_out[NN];
__device__ int g_cnt_in [NN];
__device__ int g_cursor [NN];
__device__ int g_rowptr [NN + 1];
__device__ int g_blocksum[NB];
__device__ int g_esrc[EMAX];                    // src indices sorted by dst
__device__ int g_is64;

__device__ __forceinline__ int load_idx(const void* p, int i, int is64) {
    return is64 ? (int)((const long long*)p)[i] : ((const int*)p)[i];
}

// ---------------- prep: zero counts + detect idx width + W transpose->fp16 ---
__global__ void prep_kernel(const void* src, int E,
                            const float* __restrict__ W0,
                            const float* __restrict__ W1,
                            const float* __restrict__ W2) {
    if (blockIdx.x == 0) {
        int tid = threadIdx.x;
        if (tid == 0) {
            const long long* p = (const long long*)src;
            int n = E < 8 ? E : 8;
            int ok = 1;
            for (int j = 0; j < n; j++) {
                long long v = p[j];
                if (v < 0 || v >= (long long)NN) { ok = 0; break; }
            }
            g_is64 = ok;
        }
        // Wt[n][k] = W[k][n], fp32 -> fp16
        for (int i = tid; i < 64 * 128; i += 256) {
            int n = i / 128, k = i % 128;
            g_wt0[i] = __float2half_rn(W0[k * 64 + n]);
        }
        for (int i = tid; i < 64 * 64; i += 256) {
            int n = i / 64, k = i % 64;
            g_wt1[i] = __float2half_rn(W1[k * 64 + n]);
        }
        for (int i = tid; i < 40 * 64; i += 256) {
            int n = i / 64, k = i % 64;
            g_wt2[i] = __float2half_rn(W2[k * 40 + n]);
        }
        return;
    }
    int i = (blockIdx.x - 1) * blockDim.x + threadIdx.x;
    if (i < NN) { g_cnt_out[i] = 0; g_cnt_in[i] = 0; }
}

// ---------------- degree histograms ------------------------------------------
__global__ void hist_kernel(const void* __restrict__ src,
                            const void* __restrict__ dst, int E) {
    int e = blockIdx.x * blockDim.x + threadIdx.x;
    if (e >= E) return;
    int is64 = g_is64;
    atomicAdd(&g_cnt_out[load_idx(src, e, is64)], 1);
    atomicAdd(&g_cnt_in [load_idx(dst, e, is64)], 1);
}

// ---------------- tensor-core GEMM: Y = (X @ W) [*ns], fp16 out ---------------
// 256 thr = 8 warps; block covers 128 rows; warp w -> m16 tile; n in 8-col tiles.
__device__ __forceinline__ void mma16816(
        float& c0, float& c1, float& c2, float& c3,
        uint32_t a0, uint32_t a1, uint32_t a2, uint32_t a3,
        uint32_t b0, uint32_t b1) {
    asm volatile(
        "mma.sync.aligned.m16n8k16.row.col.f32.f16.f16.f32 "
        "{%0,%1,%2,%3}, {%4,%5,%6,%7}, {%8,%9}, {%0,%1,%2,%3};"
        : "+f"(c0), "+f"(c1), "+f"(c2), "+f"(c3)
        : "r"(a0), "r"(a1), "r"(a2), "r"(a3), "r"(b0), "r"(b1));
}

template<int IN, int OUT, bool XF32, bool SCALE>
__global__ void __launch_bounds__(256) gemm_mma_kernel(
        const void* __restrict__ Xv, const __half* __restrict__ Wt,
        __half2* __restrict__ Yh) {
    extern __shared__ __half sh[];
    constexpr int SX = IN + 8;              // half stride; SX/2 mod 32 == 4
    __half* Xs = sh;                        // 128 * SX
    __half* Bs = sh + 128 * SX;             // OUT * SX
    int tid = threadIdx.x;
    int row0 = blockIdx.x * 128;

    for (int i = tid; i < OUT * (IN / 8); i += 256) {
        int n = i / (IN / 8), c = i % (IN / 8);
        *(uint4*)&Bs[n * SX + c * 8] = *(const uint4*)&Wt[n * IN + c * 8];
    }
    if (XF32) {
        const float* X = (const float*)Xv;
        for (int i = tid; i < 128 * (IN / 4); i += 256) {
            int r = i / (IN / 4), c = i % (IN / 4);
            int gr = row0 + r;
            float4 v = (gr < NN) ? __ldg((const float4*)&X[(size_t)gr * IN + c * 4])
                                 : make_float4(0.f, 0.f, 0.f, 0.f);
            *(__half2*)&Xs[r * SX + c * 4]     = __floats2half2_rn(v.x, v.y);
            *(__half2*)&Xs[r * SX + c * 4 + 2] = __floats2half2_rn(v.z, v.w);
        }
    } else {
        const __half* X = (const __half*)Xv;
        for (int i = tid; i < 128 * (IN / 8); i += 256) {
            int r = i / (IN / 8), c = i % (IN / 8);
            int gr = row0 + r;
            uint4 v = (gr < NN) ? *(const uint4*)&X[(size_t)gr * IN + c * 8]
                                : make_uint4(0u, 0u, 0u, 0u);
            *(uint4*)&Xs[r * SX + c * 8] = v;
        }
    }
    __syncthreads();

    int warp = tid >> 5, lane = tid & 31;
    int g = lane >> 2, t = lane & 3;
    int m0 = warp * 16;
    constexpr int NT = OUT / 8;
    float acc[NT][4];
    #pragma unroll
    for (int nt = 0; nt < NT; nt++) {
        acc[nt][0] = 0.f; acc[nt][1] = 0.f; acc[nt][2] = 0.f; acc[nt][3] = 0.f;
    }

    #pragma unroll
    for (int k0 = 0; k0 < IN; k0 += 16) {
        const __half* ar0 = &Xs[(m0 + g) * SX + k0];
        const __half* ar8 = ar0 + 8 * SX;
        uint32_t a0 = *(const uint32_t*)&ar0[2 * t];
        uint32_t a1 = *(const uint32_t*)&ar8[2 * t];
        uint32_t a2 = *(const uint32_t*)&ar0[2 * t + 8];
        uint32_t a3 = *(const uint32_t*)&ar8[2 * t + 8];
        #pragma unroll
        for (int nt = 0; nt < NT; nt++) {
            const __half* br = &Bs[(nt * 8 + g) * SX + k0];
            uint32_t b0 = *(const uint32_t*)&br[2 * t];
            uint32_t b1 = *(const uint32_t*)&br[2 * t + 8];
            mma16816(acc[nt][0], acc[nt][1], acc[nt][2], acc[nt][3],
                     a0, a1, a2, a3, b0, b1);
        }
    }

    int r0 = row0 + m0 + g, r1 = r0 + 8;
    float s0 = 1.f, s1 = 1.f;
    if (SCALE) {
        if (r0 < NN) s0 = g_ns[r0];
        if (r1 < NN) s1 = g_ns[r1];
    }
    constexpr int STR = OUT / 2;
    #pragma unroll
    for (int nt = 0; nt < NT; nt++) {
        int cp = nt * 4 + t;                // half2 column index
        if (r0 < NN)
            Yh[(size_t)r0 * STR + cp] = __floats2half2_rn(acc[nt][0] * s0,
                                                          acc[nt][1] * s0);
        if (r1 < NN)
            Yh[(size_t)r1 * STR + cp] = __floats2half2_rn(acc[nt][2] * s1,
                                                          acc[nt][3] * s1);
    }
}

// ---------------- exclusive scan of cnt_in -> rowptr --------------------------
__global__ void __launch_bounds__(SCAN_BS) scan1_kernel() {
    __shared__ int sh[SCAN_BS];
    int tid = threadIdx.x;
    int i = blockIdx.x * SCAN_BS + tid;
    int v = (i < NN) ? g_cnt_in[i] : 0;
    sh[tid] = v;
    __syncthreads();
    #pragma unroll
    for (int off = 1; off < SCAN_BS; off <<= 1) {
        int t = (tid >= off) ? sh[tid - off] : 0;
        __syncthreads();
        sh[tid] += t;
        __syncthreads();
    }
    if (i < NN) g_rowptr[i] = sh[tid] - v;          // exclusive (per-block)
    if (tid == SCAN_BS - 1) g_blocksum[blockIdx.x] = sh[tid];
}

__global__ void scan2_kernel() {
    int lane = threadIdx.x;
    int carry = 0;
    const int CH = (NB + 31) / 32;
    for (int c = 0; c < CH; c++) {
        int i = c * 32 + lane;
        int v0 = (i < NB) ? g_blocksum[i] : 0;
        int v = v0;
        #pragma unroll
        for (int off = 1; off < 32; off <<= 1) {
            int t = __shfl_up_sync(0xffffffffu, v, off);
            if (lane >= off) v += t;
        }
        if (i < NB) g_blocksum[i] = carry + v - v0;  // exclusive
        carry += __shfl_sync(0xffffffffu, v, 31);
    }
    if (lane == 0) g_rowptr[NN] = carry;             // == E
}

// scan3: finalize rowptr, norms, cursors, AND scale Y0 (fp16) by ns
__global__ void __launch_bounds__(SCAN_BS) scan3_kernel(__half2* __restrict__ Yh) {
    int i = blockIdx.x * SCAN_BS + threadIdx.x;
    if (i >= NN) return;
    g_rowptr[i] += g_blocksum[blockIdx.x];
    g_cursor[i] = 0;
    int o = g_cnt_out[i], d = g_cnt_in[i];
    float nsv = (o > 0) ? rsqrtf((float)o) : 0.f;
    g_ns[i] = nsv;
    g_nd[i] = (d > 0) ? rsqrtf((float)d) : 0.f;
    __half2 h2s = __floats2half2_rn(nsv, nsv);
    __half2* yr = &Yh[(size_t)i * 32];
    #pragma unroll
    for (int j = 0; j < 32; j++)
        yr[j] = __hmul2(yr[j], h2s);
}

// ---------------- edge placement: CSR by dst ----------------------------------
__global__ void place_kernel(const void* __restrict__ src,
                             const void* __restrict__ dst, int E) {
    int e = blockIdx.x * blockDim.x + threadIdx.x;
    if (e >= E) return;
    int is64 = g_is64;
    int s = load_idx(src, e, is64);
    int d = load_idx(dst, e, is64);
    int pos = g_rowptr[d] + atomicAdd(&g_cursor[d], 1);
    g_esrc[pos] = s;
}

// ---------------- fused SpMM-gather (fp16) + epilogue -------------------------
// One warp per dst row; lane covers 2 cols via half2; fp32 accumulate.
// O16: write __half2 (hidden layers); else fp32 (final output).
template<int OUT, bool RELU, bool O16>
__global__ void __launch_bounds__(256) spmm_epi_kernel(
        const __half2* __restrict__ Yh, const float* __restrict__ bias,
        void* __restrict__ OutV) {
    int row = blockIdx.x * 8 + (threadIdx.x >> 5);
    if (row >= NN) return;
    int lane = threadIdx.x & 31;
    constexpr int STR = OUT / 2;
    int c0 = 2 * lane;
    bool valid = lane < STR;

    int beg = g_rowptr[row], end = g_rowptr[row + 1];
    float a0 = 0.f, a1 = 0.f, b0_ = 0.f, b1_ = 0.f;

    for (int base = beg; base < end; base += 32) {
        int rem = end - base; if (rem > 32) rem = 32;
        int my = (lane < rem) ? g_esrc[base + lane] : 0;
        int j = 0;
        for (; j + 4 <= rem; j += 4) {
            int s0 = __shfl_sync(0xffffffffu, my, j);
            int s1 = __shfl_sync(0xffffffffu, my, j + 1);
            int s2 = __shfl_sync(0xffffffffu, my, j + 2);
            int s3 = __shfl_sync(0xffffffffu, my, j + 3);
            if (valid) {
                float2 v0 = __half22float2(__ldg(&Yh[(size_t)s0 * STR + lane]));
                float2 v1 = __half22float2(__ldg(&Yh[(size_t)s1 * STR + lane]));
                float2 v2 = __half22float2(__ldg(&Yh[(size_t)s2 * STR + lane]));
                float2 v3 = __half22float2(__ldg(&Yh[(size_t)s3 * STR + lane]));
                a0 += v0.x; a1 += v0.y;
                b0_ += v1.x; b1_ += v1.y;
                a0 += v2.x; a1 += v2.y;
                b0_ += v3.x; b1_ += v3.y;
            }
        }
        for (; j < rem; j++) {
            int s = __shfl_sync(0xffffffffu, my, j);
            if (valid) {
                float2 v = __half22float2(__ldg(&Yh[(size_t)s * STR + lane]));
                a0 += v.x; a1 += v.y;
            }
        }
    }
    a0 += b0_; a1 += b1_;

    float ndv = g_nd[row];
    float v0 = -CUDART_INF_F, v1 = -CUDART_INF_F;
    if (valid) {
        v0 = a0 * ndv + bias[c0];
        v1 = a1 * ndv + bias[c0 + 1];
        if (RELU) { v0 = fmaxf(v0, 0.f); v1 = fmaxf(v1, 0.f); }
    }
    float m = fmaxf(v0, v1);
    #pragma unroll
    for (int o = 16; o; o >>= 1) m = fmaxf(m, __shfl_xor_sync(0xffffffffu, m, o));
    float s = valid ? (__expf(v0 - m) + __expf(v1 - m)) : 0.f;
    #pragma unroll
    for (int o = 16; o; o >>= 1) s += __shfl_xor_sync(0xffffffffu, s, o);
    float ls = logf(s) + m;
    if (valid) {
        if (O16) {
            __half2* Out = (__half2*)OutV;
            Out[(size_t)row * STR + lane] = __floats2half2_rn(v0 - ls, v1 - ls);
        } else {
            float* Out = (float*)OutV;
            *(float2*)&Out[(size_t)row * OUT + c0] = make_float2(v0 - ls, v1 - ls);
        }
    }
}

// ---------------- launcher ----------------------------------------------------
extern "C" void kernel_launch(void* const* d_in, const int* in_sizes, int n_in,
                              void* d_out, int out_size) {
    const float* feats = (const float*)d_in[0];
    const void*  src   = d_in[1];
    const void*  dst   = d_in[2];
    const float* W0    = (const float*)d_in[3];
    const float* b0    = (const float*)d_in[4];
    const float* W1    = (const float*)d_in[5];
    const float* b1    = (const float*)d_in[6];
    const float* W2    = (const float*)d_in[7];
    const float* b2    = (const float*)d_in[8];
    float* out = (float*)d_out;
    int E = in_sizes[1];

    __half2* p_y = nullptr;
    __half *p_h1 = nullptr, *p_h2 = nullptr;
    __half *p_wt0 = nullptr, *p_wt1 = nullptr, *p_wt2 = nullptr;
    cudaGetSymbolAddress((void**)&p_y,   g_y);
    cudaGetSymbolAddress((void**)&p_h1,  g_h1);
    cudaGetSymbolAddress((void**)&p_h2,  g_h2);
    cudaGetSymbolAddress((void**)&p_wt0, g_wt0);
    cudaGetSymbolAddress((void**)&p_wt1, g_wt1);
    cudaGetSymbolAddress((void**)&p_wt2, g_wt2);

    const int MB = (NN + 127) / 128;  // mma gemm blocks (128 rows each)
    const int SB = (NN + 7) / 8;      // spmm blocks (warp per row)
    const int EB = (E + 255) / 256;   // per-edge blocks
    const int ZB = (NN + 255) / 256;  // zero blocks

    const int sm0 = (128 * (128 + 8) + 64 * (128 + 8)) * 2;  // 52224
    const int sm1 = (128 * (64 + 8) + 64 * (64 + 8)) * 2;    // 27648
    const int sm2 = (128 * (64 + 8) + 40 * (64 + 8)) * 2;    // 24192
    cudaFuncSetAttribute(gemm_mma_kernel<128, 64, true, false>,
                         cudaFuncAttributeMaxDynamicSharedMemorySize, sm0);
    cudaFuncSetAttribute(gemm_mma_kernel<64, 64, false, true>,
                         cudaFuncAttributeMaxDynamicSharedMemorySize, sm1);
    cudaFuncSetAttribute(gemm_mma_kernel<64, 40, false, true>,
                         cudaFuncAttributeMaxDynamicSharedMemorySize, sm2);

    // ---- prep (zero + detect + W transpose/fp16), CSR build, layer-0 GEMM
    prep_kernel<<<ZB + 1, 256>>>(src, E, W0, W1, W2);
    hist_kernel<<<EB, 256>>>(src, dst, E);
    gemm_mma_kernel<128, 64, true, false><<<MB, 256, sm0>>>(feats, p_wt0, p_y);
    scan1_kernel<<<NB, SCAN_BS>>>();
    scan2_kernel<<<1, 32>>>();
    scan3_kernel<<<NB, SCAN_BS>>>(p_y);     // + Y0 *= ns (fp16)
    place_kernel<<<EB, 256>>>(src, dst, E);

    // ---- layer 0: relu + log_softmax -> h1 (fp16)
    spmm_epi_kernel<64, true, true><<<SB, 256>>>(p_y, b0, p_h1);

    // ---- layer 1: 64 -> 64 (mma, scaled) -> spmm -> h2 (fp16)
    gemm_mma_kernel<64, 64, false, true><<<MB, 256, sm1>>>(p_h1, p_wt1, p_y);
    spmm_epi_kernel<64, true, true><<<SB, 256>>>(p_y, b1, p_h2);

    // ---- layer 2: 64 -> 40 (mma, scaled) -> spmm -> out (fp32)
    gemm_mma_kernel<64, 40, false, true><<<MB, 256, sm2>>>(p_h2, p_wt2, p_y);
    spmm_epi_kernel<40, false, false><<<SB, 256>>>(p_y, b2, out);
}